// round 4
// baseline (speedup 1.0000x reference)
#include <cuda_runtime.h>

// ---------------------------------------------------------------------------
// CML2DWithStats, round 4: packed f32x2 arithmetic (Blackwell FFMA2) on the
// round-3 paired-row skeleton.
//
//   g_{t+1} = clamp( conv3x3( m_t, K' ) + BETA*drive ),  m = g*(1-g)
//   K' = R*(1-BETA)*(EPS*K + (1-EPS)*delta_center)
//
// One CTA per (batch, channel, 64-row strip). SMEM = two 96x256 mapped
// buffers (split-quad layout, conflict-free LDS/STS.128). Each thread owns
// 3 row-pairs; a pair loads 4 input rows for 2 outputs. Conv accumulators,
// beta-init, map and stats run as packed f32x2 (1 issue slot / 2 lanes).
// ---------------------------------------------------------------------------

#define R_PARAM  3.9f
#define EPS_P    0.3f
#define BETA_P   0.15f
#define NSTEPS   15
#define CLAMP_LO 1e-4f
#define CLAMP_HI (1.0f - 1e-4f)

constexpr int W      = 256;
constexpr int HIMG   = 256;
constexpr int STRIP  = 64;
constexpr int HALO   = 16;
constexpr int BROWS  = 96;
constexpr int TXN    = 32;
constexpr int TYN    = 16;
constexpr int NTHR   = TXN * TYN;          // 512
constexpr int NPLANE = W * HIMG;
constexpr long long NTOT = 16LL * 8 * NPLANE;

typedef unsigned long long u64;

__device__ __forceinline__ u64 pk(float lo, float hi) {
    u64 r; asm("mov.b64 %0, {%1, %2};" : "=l"(r) : "f"(lo), "f"(hi)); return r;
}
__device__ __forceinline__ void unpk(u64 v, float& lo, float& hi) {
    asm("mov.b64 {%0, %1}, %2;" : "=f"(lo), "=f"(hi) : "l"(v));
}
__device__ __forceinline__ u64 ffma2(u64 a, u64 b, u64 c) {
    u64 d; asm("fma.rn.f32x2 %0, %1, %2, %3;" : "=l"(d) : "l"(a), "l"(b), "l"(c)); return d;
}
__device__ __forceinline__ u64 fmul2(u64 a, u64 b) {
    u64 d; asm("mul.rn.f32x2 %0, %1, %2;" : "=l"(d) : "l"(a), "l"(b)); return d;
}
__device__ __forceinline__ u64 fadd2(u64 a, u64 b) {
    u64 d; asm("add.rn.f32x2 %0, %1, %2;" : "=l"(d) : "l"(a), "l"(b)); return d;
}
__device__ __forceinline__ float clampg(float v) {
    return fminf(fmaxf(v, CLAMP_LO), CLAMP_HI);
}

__global__ __launch_bounds__(NTHR, 1)
void cml_fused_kernel(const float* __restrict__ drive,
                      const float* __restrict__ Klocal,
                      float* __restrict__ out)
{
    extern __shared__ float sm[];
    float* MB0 = sm;
    float* MB1 = sm + BROWS * W;

    const int tx = threadIdx.x;
    const int ty = threadIdx.y;
    const int strip = blockIdx.x;
    const int c     = blockIdx.y;
    const int b     = blockIdx.z;
    const int row0  = strip * STRIP - HALO;
    const int x4    = tx * 4;
    const int x0    = tx * 8;

    // Folded kernel K' = R*(1-BETA)*(EPS*K + (1-EPS)*delta), packed (v,v)
    u64 kkp[3][3];
    {
        const float* kc = Klocal + c * 9;
        #pragma unroll
        for (int j = 0; j < 3; ++j)
            #pragma unroll
            for (int i = 0; i < 3; ++i) {
                float v = EPS_P * kc[j * 3 + i];
                if (j == 1 && i == 1) v += (1.0f - EPS_P);
                v *= R_PARAM * (1.0f - BETA_P);
                kkp[j][i] = pk(v, v);
            }
    }
    const u64 BETA2 = pk(BETA_P, BETA_P);
    const u64 NEG1  = pk(-1.0f, -1.0f);

    const long long plane = (long long)(b * 8 + c) * NPLANE;
    const float* dpl = drive + plane;

    // ---- init: MB0 <- mapped(drive) on in-image rows, 0 elsewhere; MB1 <- 0 ----
    #pragma unroll
    for (int k = 0; k < 6; ++k) {
        int r  = ty + TYN * k;
        int ir = row0 + r;
        float* p0 = MB0 + r * W;
        float* p1 = MB1 + r * W;
        float4 z = make_float4(0.f, 0.f, 0.f, 0.f);
        *reinterpret_cast<float4*>(p1 + x4)       = z;
        *reinterpret_cast<float4*>(p1 + 128 + x4) = z;
        if ((unsigned)ir < (unsigned)HIMG) {
            const float* dr = dpl + (long long)ir * W + x0;
            float4 dA = *reinterpret_cast<const float4*>(dr);
            float4 dB = *reinterpret_cast<const float4*>(dr + 4);
            float4 mA, mB;
            mA.x = fmaf(-dA.x, dA.x, dA.x);  mA.y = fmaf(-dA.y, dA.y, dA.y);
            mA.z = fmaf(-dA.z, dA.z, dA.z);  mA.w = fmaf(-dA.w, dA.w, dA.w);
            mB.x = fmaf(-dB.x, dB.x, dB.x);  mB.y = fmaf(-dB.y, dB.y, dB.y);
            mB.z = fmaf(-dB.z, dB.z, dB.z);  mB.w = fmaf(-dB.w, dB.w, dB.w);
            *reinterpret_cast<float4*>(p0 + x4)       = mA;
            *reinterpret_cast<float4*>(p0 + 128 + x4) = mB;
        } else {
            *reinterpret_cast<float4*>(p0 + x4)       = z;
            *reinterpret_cast<float4*>(p0 + 128 + x4) = z;
        }
    }
    __syncthreads();

    // stats: 2 interior pair-slots per thread, packed. [rowInPair*4 + quadpair]
    u64 sum0[8], ssq0[8], sum1[8], ssq1[8];
    #pragma unroll
    for (int i = 0; i < 8; ++i) {
        sum0[i] = 0ull; ssq0[i] = 0ull; sum1[i] = 0ull; ssq1[i] = 0ull;
    }

    // apply one loaded row (packs A0..A3, S0..S4 live) to packed acc[4]
    #define APPLY(acc, kp)                                                     \
        {                                                                      \
            acc[0] = ffma2(kp[0], S0, ffma2(kp[1], A0, ffma2(kp[2], S1, acc[0]))); \
            acc[1] = ffma2(kp[0], S1, ffma2(kp[1], A1, ffma2(kp[2], S2, acc[1]))); \
            acc[2] = ffma2(kp[0], S2, ffma2(kp[1], A2, ffma2(kp[2], S3, acc[2]))); \
            acc[3] = ffma2(kp[0], S3, ffma2(kp[1], A3, ffma2(kp[2], S4, acc[3]))); \
        }

    // conv for a pair of rows r0,r0+1: loads rows r0-1..r0+2 once each
    #define PAIR_CONV(Min, r0, acc0, acc1)                                     \
        {                                                                      \
            _Pragma("unroll")                                                  \
            for (int jr = 0; jr < 4; ++jr) {                                   \
                const float* rp = (Min) + ((r0) - 1 + jr) * W;                 \
                float4 qa = *reinterpret_cast<const float4*>(rp + x4);         \
                float4 qb = *reinterpret_cast<const float4*>(rp + 128 + x4);   \
                float lm = __shfl_up_sync(0xffffffffu, qb.w, 1);               \
                float rm = __shfl_down_sync(0xffffffffu, qa.x, 1);             \
                if (tx == 0)  lm = 0.f;                                        \
                if (tx == 31) rm = 0.f;                                        \
                u64 A0 = pk(qa.x, qa.y), A1 = pk(qa.z, qa.w);                  \
                u64 A2 = pk(qb.x, qb.y), A3 = pk(qb.z, qb.w);                  \
                u64 S0 = pk(lm,  qa.x), S1 = pk(qa.y, qa.z);                   \
                u64 S2 = pk(qa.w, qb.x), S3 = pk(qb.y, qb.z);                  \
                u64 S4 = pk(qb.w, rm);                                         \
                if (jr < 3) APPLY(acc0, kkp[jr])                               \
                if (jr > 0) APPLY(acc1, kkp[jr - 1])                           \
            }                                                                  \
        }

    #define LOAD_DRIVE_ACC(ir, acc)                                            \
        {                                                                      \
            const float* dr = dpl + (long long)(ir) * W + x0;                  \
            float4 dA = *reinterpret_cast<const float4*>(dr);                  \
            float4 dB = *reinterpret_cast<const float4*>(dr + 4);              \
            acc[0] = fmul2(BETA2, pk(dA.x, dA.y));                             \
            acc[1] = fmul2(BETA2, pk(dA.z, dA.w));                             \
            acc[2] = fmul2(BETA2, pk(dB.x, dB.y));                             \
            acc[3] = fmul2(BETA2, pk(dB.z, dB.w));                             \
        }

    // clamp packed acc -> gP; g2P = g*g; mmP = g - g*g; store mm row
    #define FINISH_ROW(acc, gP, g2P, op)                                       \
        {                                                                      \
            _Pragma("unroll")                                                  \
            for (int q = 0; q < 4; ++q) {                                      \
                float a, bql;                                                  \
                unpk(acc[q], a, bql);                                          \
                gP[q]  = pk(clampg(a), clampg(bql));                           \
                g2P[q] = fmul2(gP[q], gP[q]);                                  \
            }                                                                  \
            float4 o0, o1;                                                     \
            u64 t0 = ffma2(g2P[0], NEG1, gP[0]);                               \
            u64 t1 = ffma2(g2P[1], NEG1, gP[1]);                               \
            u64 t2 = ffma2(g2P[2], NEG1, gP[2]);                               \
            u64 t3 = ffma2(g2P[3], NEG1, gP[3]);                               \
            unpk(t0, o0.x, o0.y);  unpk(t1, o0.z, o0.w);                       \
            unpk(t2, o1.x, o1.y);  unpk(t3, o1.z, o1.w);                       \
            *reinterpret_cast<float4*>((op) + x4)       = o0;                  \
            *reinterpret_cast<float4*>((op) + 128 + x4) = o1;                  \
        }

    #define STATS_ADD(sumA, ssqA, gP0, g2P0, gP1, g2P1)                        \
        {                                                                      \
            _Pragma("unroll")                                                  \
            for (int q = 0; q < 4; ++q) {                                      \
                sumA[q]     = fadd2(sumA[q],     gP0[q]);                      \
                ssqA[q]     = fadd2(ssqA[q],     g2P0[q]);                     \
                sumA[q + 4] = fadd2(sumA[q + 4], gP1[q]);                      \
                ssqA[q + 4] = fadd2(ssqA[q + 4], g2P1[q]);                     \
            }                                                                  \
        }

    // ---- steps 0..13 ----
    #pragma unroll 1
    for (int t = 0; t < NSTEPS - 1; ++t) {
        const float* Min  = (t & 1) ? MB1 : MB0;
        float*       Mout = (t & 1) ? MB0 : MB1;
        const int lo = 2 + t, hi = 93 - t;

        #pragma unroll
        for (int k = 0; k < 3; ++k) {
            const int p  = ty + 16 * k;
            const int r0 = 2 * p;
            const int r1 = r0 + 1;
            const int ir0 = row0 + r0;
            if (r1 < lo || r0 > hi) continue;                    // outside window
            if ((unsigned)ir0 >= (unsigned)HIMG) continue;       // out of image

            u64 acc0[4], acc1[4];
            LOAD_DRIVE_ACC(ir0, acc0)
            LOAD_DRIVE_ACC(ir0 + 1, acc1)

            PAIR_CONV(Min, r0, acc0, acc1)

            u64 gP0[4], g2P0[4], gP1[4], g2P1[4];
            FINISH_ROW(acc0, gP0, g2P0, Mout + r0 * W)
            FINISH_ROW(acc1, gP1, g2P1, Mout + r1 * W)

            // stats: interior pairs (rows 16..79). ty<8 -> k 1,2 ; ty>=8 -> k 0,1
            if (k == 0) {
                if (ty >= 8) STATS_ADD(sum0, ssq0, gP0, g2P0, gP1, g2P1)
            } else if (k == 1) {
                if (ty < 8) { STATS_ADD(sum0, ssq0, gP0, g2P0, gP1, g2P1) }
                else        { STATS_ADD(sum1, ssq1, gP0, g2P0, gP1, g2P1) }
            } else {
                if (ty < 8) STATS_ADD(sum1, ssq1, gP0, g2P0, gP1, g2P1)
            }
        }
        __syncthreads();
    }

    // ---- final step t=14: interior pairs only, write all 5 outputs ----
    {
        const float* Min = MB0;                 // t=14 even -> read MB0
        const float inv = 1.0f / (float)NSTEPS;

        #pragma unroll
        for (int k = 0; k < 3; ++k) {
            bool inter0 = (k == 0 && ty >= 8) || (k == 1 && ty < 8);
            bool inter1 = (k == 1 && ty >= 8) || (k == 2 && ty < 8);
            if (!inter0 && !inter1) continue;
            u64* sumA = inter0 ? sum0 : sum1;
            u64* ssqA = inter0 ? ssq0 : ssq1;

            const int p  = ty + 16 * k;
            const int r0 = 2 * p;
            const int ir0 = row0 + r0;

            u64 acc0[4], acc1[4];
            LOAD_DRIVE_ACC(ir0, acc0)
            LOAD_DRIVE_ACC(ir0 + 1, acc1)

            PAIR_CONV(Min, r0, acc0, acc1)

            #pragma unroll
            for (int half = 0; half < 2; ++half) {
                u64* acc = half ? acc1 : acc0;
                const int off = half * 4;
                long long idx = plane + (long long)(ir0 + half) * W + x0;

                float g[8], mean[8], var[8], del[8];
                #pragma unroll
                for (int q = 0; q < 4; ++q) {
                    float a, bq;
                    unpk(acc[q], a, bq);
                    float ga = clampg(a), gb = clampg(bq);
                    g[2 * q] = ga;  g[2 * q + 1] = gb;

                    float s0, s1, q0, q1;
                    unpk(sumA[off + q], s0, s1);
                    unpk(ssqA[off + q], q0, q1);
                    s0 += ga;  s1 += gb;
                    q0 = fmaf(ga, ga, q0);  q1 = fmaf(gb, gb, q1);
                    mean[2 * q]     = s0 * inv;
                    mean[2 * q + 1] = s1 * inv;
                    var[2 * q]      = fmaf(-mean[2 * q],     mean[2 * q],     q0 * inv);
                    var[2 * q + 1]  = fmaf(-mean[2 * q + 1], mean[2 * q + 1], q1 * inv);
                }
                {
                    const float* dr = dpl + (long long)(ir0 + half) * W + x0;
                    float4 dA = *reinterpret_cast<const float4*>(dr);
                    float4 dB = *reinterpret_cast<const float4*>(dr + 4);
                    del[0] = g[0] - dA.x;  del[1] = g[1] - dA.y;
                    del[2] = g[2] - dA.z;  del[3] = g[3] - dA.w;
                    del[4] = g[4] - dB.x;  del[5] = g[5] - dB.y;
                    del[6] = g[6] - dB.z;  del[7] = g[7] - dB.w;
                }
                *reinterpret_cast<float4*>(out + idx)                = make_float4(g[0], g[1], g[2], g[3]);
                *reinterpret_cast<float4*>(out + idx + 4)            = make_float4(g[4], g[5], g[6], g[7]);
                *reinterpret_cast<float4*>(out + NTOT + idx)         = make_float4(mean[0], mean[1], mean[2], mean[3]);
                *reinterpret_cast<float4*>(out + NTOT + idx + 4)     = make_float4(mean[4], mean[5], mean[6], mean[7]);
                *reinterpret_cast<float4*>(out + 2 * NTOT + idx)     = make_float4(var[0], var[1], var[2], var[3]);
                *reinterpret_cast<float4*>(out + 2 * NTOT + idx + 4) = make_float4(var[4], var[5], var[6], var[7]);
                *reinterpret_cast<float4*>(out + 3 * NTOT + idx)     = make_float4(del[0], del[1], del[2], del[3]);
                *reinterpret_cast<float4*>(out + 3 * NTOT + idx + 4) = make_float4(del[4], del[5], del[6], del[7]);
                *reinterpret_cast<float4*>(out + 4 * NTOT + idx)     = make_float4(del[0], del[1], del[2], del[3]);
                *reinterpret_cast<float4*>(out + 4 * NTOT + idx + 4) = make_float4(del[4], del[5], del[6], del[7]);
            }
        }
    }
}

extern "C" void kernel_launch(void* const* d_in, const int* in_sizes, int n_in,
                              void* d_out, int out_size)
{
    const float* drive  = (const float*)d_in[0];   // [16,8,256,256] f32
    const float* Klocal = (const float*)d_in[1];   // [8,1,3,3] f32
    float* out = (float*)d_out;                    // 5 x [16,8,256,256] f32

    const int smem_bytes = 2 * BROWS * W * (int)sizeof(float);   // 196608
    cudaFuncSetAttribute(cml_fused_kernel,
                         cudaFuncAttributeMaxDynamicSharedMemorySize, smem_bytes);

    dim3 grid(HIMG / STRIP, 8, 16);    // 4 strips x 8 ch x 16 batch = 512 CTAs
    dim3 block(TXN, TYN);              // 512 threads
    cml_fused_kernel<<<grid, block, smem_bytes>>>(drive, Klocal, out);
}

// round 5
// speedup vs baseline: 1.0388x; 1.0388x over previous
#include <cuda_runtime.h>

// ---------------------------------------------------------------------------
// CML2DWithStats, round 5: round-3 scalar skeleton + deferred drive add.
//
//   g_{t+1} = clamp( conv3x3( m_t, K' ) + BETA*drive ),  m = g*(1-g)
//   K' = R*(1-BETA)*(EPS*K + (1-EPS)*delta_center)
//
// One CTA per (batch, channel, 64-row strip). SMEM = two 96x256 mapped
// buffers (split-quad layout: row*256 + [tx*4 | 128 + tx*4], conflict-free).
// Each thread owns 3 row-pairs (p = ty + 16k); a pair loads 4 input rows for
// 2 outputs (4 LDS.128 + 4 SHFL per row).
//
// Deferred drive: raw drive is loaded at pair START (LDG.128 x4, L2-resident)
// but only consumed at pair END (g = clamp(fma(beta, d, conv))), so the
// ~240-cycle L2 latency hides behind the 144-FMA conv.
// ---------------------------------------------------------------------------

#define R_PARAM  3.9f
#define EPS_P    0.3f
#define BETA_P   0.15f
#define NSTEPS   15
#define CLAMP_LO 1e-4f
#define CLAMP_HI (1.0f - 1e-4f)

constexpr int W      = 256;
constexpr int HIMG   = 256;
constexpr int STRIP  = 64;
constexpr int HALO   = 16;
constexpr int BROWS  = 96;
constexpr int TXN    = 32;
constexpr int TYN    = 16;
constexpr int NTHR   = TXN * TYN;          // 512
constexpr int NPLANE = W * HIMG;
constexpr long long NTOT = 16LL * 8 * NPLANE;

__device__ __forceinline__ float clampg(float v) {
    return fminf(fmaxf(v, CLAMP_LO), CLAMP_HI);
}

__global__ __launch_bounds__(NTHR, 1)
void cml_fused_kernel(const float* __restrict__ drive,
                      const float* __restrict__ Klocal,
                      float* __restrict__ out)
{
    extern __shared__ float sm[];
    float* MB0 = sm;
    float* MB1 = sm + BROWS * W;

    const int tx = threadIdx.x;
    const int ty = threadIdx.y;
    const int strip = blockIdx.x;
    const int c     = blockIdx.y;
    const int b     = blockIdx.z;
    const int row0  = strip * STRIP - HALO;
    const int x4    = tx * 4;
    const int x0    = tx * 8;

    // Folded kernel K' = R*(1-BETA)*(EPS*K + (1-EPS)*delta)
    float kk[3][3];
    {
        const float* kc = Klocal + c * 9;
        #pragma unroll
        for (int j = 0; j < 3; ++j)
            #pragma unroll
            for (int i = 0; i < 3; ++i) {
                float v = EPS_P * kc[j * 3 + i];
                if (j == 1 && i == 1) v += (1.0f - EPS_P);
                kk[j][i] = R_PARAM * (1.0f - BETA_P) * v;
            }
    }

    const long long plane = (long long)(b * 8 + c) * NPLANE;
    const float* dpl = drive + plane;

    // static per-thread pair geometry (independent of step)
    // pair k: p = ty + 16k, rows r0 = 2p, r0+1 ; image rows ir0, ir0+1
    int  r0a[3], ir0a[3];
    bool inimg[3];
    #pragma unroll
    for (int k = 0; k < 3; ++k) {
        int p  = ty + 16 * k;
        r0a[k]  = 2 * p;
        ir0a[k] = row0 + 2 * p;
        inimg[k] = (unsigned)ir0a[k] < (unsigned)HIMG;
    }

    // ---- init: MB0 <- mapped(drive) on in-image rows, 0 elsewhere; MB1 <- 0 ----
    #pragma unroll
    for (int k = 0; k < 6; ++k) {
        int r  = ty + TYN * k;
        int ir = row0 + r;
        float* p0 = MB0 + r * W;
        float* p1 = MB1 + r * W;
        float4 z = make_float4(0.f, 0.f, 0.f, 0.f);
        *reinterpret_cast<float4*>(p1 + x4)       = z;
        *reinterpret_cast<float4*>(p1 + 128 + x4) = z;
        if ((unsigned)ir < (unsigned)HIMG) {
            const float* dr = dpl + (long long)ir * W + x0;
            float4 dA = *reinterpret_cast<const float4*>(dr);
            float4 dB = *reinterpret_cast<const float4*>(dr + 4);
            float4 mA, mB;
            mA.x = fmaf(-dA.x, dA.x, dA.x);  mA.y = fmaf(-dA.y, dA.y, dA.y);
            mA.z = fmaf(-dA.z, dA.z, dA.z);  mA.w = fmaf(-dA.w, dA.w, dA.w);
            mB.x = fmaf(-dB.x, dB.x, dB.x);  mB.y = fmaf(-dB.y, dB.y, dB.y);
            mB.z = fmaf(-dB.z, dB.z, dB.z);  mB.w = fmaf(-dB.w, dB.w, dB.w);
            *reinterpret_cast<float4*>(p0 + x4)       = mA;
            *reinterpret_cast<float4*>(p0 + 128 + x4) = mB;
        } else {
            *reinterpret_cast<float4*>(p0 + x4)       = z;
            *reinterpret_cast<float4*>(p0 + 128 + x4) = z;
        }
    }
    __syncthreads();

    // stats: 2 interior pair-slots per thread. [rowInPair*8 + i]
    float sum0[16], ssq0[16], sum1[16], ssq1[16];
    #pragma unroll
    for (int i = 0; i < 16; ++i) {
        sum0[i] = 0.f; ssq0[i] = 0.f; sum1[i] = 0.f; ssq1[i] = 0.f;
    }

    // accumulate one loaded row (m0..m7,lm,rm live) into acc with kernel row cc
    #define ACCROW(acc, cc)                                                    \
        {                                                                      \
            float c0 = (cc)[0], c1 = (cc)[1], c2 = (cc)[2];                    \
            acc[0] = fmaf(c0, lm, fmaf(c1, m0, fmaf(c2, m1, acc[0])));         \
            acc[1] = fmaf(c0, m0, fmaf(c1, m1, fmaf(c2, m2, acc[1])));         \
            acc[2] = fmaf(c0, m1, fmaf(c1, m2, fmaf(c2, m3, acc[2])));         \
            acc[3] = fmaf(c0, m2, fmaf(c1, m3, fmaf(c2, m4, acc[3])));         \
            acc[4] = fmaf(c0, m3, fmaf(c1, m4, fmaf(c2, m5, acc[4])));         \
            acc[5] = fmaf(c0, m4, fmaf(c1, m5, fmaf(c2, m6, acc[5])));         \
            acc[6] = fmaf(c0, m5, fmaf(c1, m6, fmaf(c2, m7, acc[6])));         \
            acc[7] = fmaf(c0, m6, fmaf(c1, m7, fmaf(c2, rm, acc[7])));         \
        }

    // conv for a pair of rows r0,r0+1: loads rows r0-1..r0+2 once each
    #define PAIR_CONV(Min, r0, acc0, acc1)                                     \
        {                                                                      \
            _Pragma("unroll")                                                  \
            for (int jr = 0; jr < 4; ++jr) {                                   \
                const float* rp = (Min) + ((r0) - 1 + jr) * W;                 \
                float4 qa = *reinterpret_cast<const float4*>(rp + x4);         \
                float4 qb = *reinterpret_cast<const float4*>(rp + 128 + x4);   \
                float m0 = qa.x, m1 = qa.y, m2 = qa.z, m3 = qa.w;              \
                float m4 = qb.x, m5 = qb.y, m6 = qb.z, m7 = qb.w;              \
                float lm = __shfl_up_sync(0xffffffffu, m7, 1);                 \
                float rm = __shfl_down_sync(0xffffffffu, m0, 1);               \
                if (tx == 0)  lm = 0.f;                                        \
                if (tx == 31) rm = 0.f;                                        \
                if (jr < 3) ACCROW(acc0, kk[jr])                               \
                if (jr > 0) ACCROW(acc1, kk[jr - 1])                           \
            }                                                                  \
        }

    // raw drive load (consumed only at pair end)
    #define LOAD_DRIVE_RAW(ir, dv)                                             \
        {                                                                      \
            const float* dr = dpl + (long long)(ir) * W + x0;                  \
            float4 dA = *reinterpret_cast<const float4*>(dr);                  \
            float4 dB = *reinterpret_cast<const float4*>(dr + 4);              \
            dv[0] = dA.x;  dv[1] = dA.y;  dv[2] = dA.z;  dv[3] = dA.w;         \
            dv[4] = dB.x;  dv[5] = dB.y;  dv[6] = dB.z;  dv[7] = dB.w;         \
        }

    #define STATS_ADD(sumA, ssqA, g0, g1)                                      \
        {                                                                      \
            _Pragma("unroll")                                                  \
            for (int i = 0; i < 8; ++i) {                                      \
                sumA[i]     += g0[i];  ssqA[i]     = fmaf(g0[i], g0[i], ssqA[i]); \
                sumA[i + 8] += g1[i];  ssqA[i + 8] = fmaf(g1[i], g1[i], ssqA[i + 8]); \
            }                                                                  \
        }

    // ---- steps 0..13 ----
    #pragma unroll 1
    for (int t = 0; t < NSTEPS - 1; ++t) {
        const float* Min  = (t & 1) ? MB1 : MB0;
        float*       Mout = (t & 1) ? MB0 : MB1;
        const int lo = 2 + t, hi = 93 - t;

        #pragma unroll
        for (int k = 0; k < 3; ++k) {
            const int r0 = r0a[k];
            if (r0 + 1 < lo || r0 > hi) continue;   // outside shrinking window
            if (!inimg[k]) continue;                // out of image (pair-aligned)
            const int ir0 = ir0a[k];

            float dv0[8], dv1[8];
            LOAD_DRIVE_RAW(ir0, dv0)
            LOAD_DRIVE_RAW(ir0 + 1, dv1)

            float acc0[8] = {0.f, 0.f, 0.f, 0.f, 0.f, 0.f, 0.f, 0.f};
            float acc1[8] = {0.f, 0.f, 0.f, 0.f, 0.f, 0.f, 0.f, 0.f};
            PAIR_CONV(Min, r0, acc0, acc1)

            float g0[8], g1[8], mm0[8], mm1[8];
            #pragma unroll
            for (int i = 0; i < 8; ++i) {
                g0[i]  = clampg(fmaf(BETA_P, dv0[i], acc0[i]));
                g1[i]  = clampg(fmaf(BETA_P, dv1[i], acc1[i]));
                mm0[i] = fmaf(-g0[i], g0[i], g0[i]);
                mm1[i] = fmaf(-g1[i], g1[i], g1[i]);
            }
            float* op0 = Mout + r0 * W;
            float* op1 = Mout + (r0 + 1) * W;
            *reinterpret_cast<float4*>(op0 + x4)       = make_float4(mm0[0], mm0[1], mm0[2], mm0[3]);
            *reinterpret_cast<float4*>(op0 + 128 + x4) = make_float4(mm0[4], mm0[5], mm0[6], mm0[7]);
            *reinterpret_cast<float4*>(op1 + x4)       = make_float4(mm1[0], mm1[1], mm1[2], mm1[3]);
            *reinterpret_cast<float4*>(op1 + 128 + x4) = make_float4(mm1[4], mm1[5], mm1[6], mm1[7]);

            // stats: interior pairs (rows 16..79). ty<8 -> k 1,2 ; ty>=8 -> k 0,1
            if (k == 0) {
                if (ty >= 8) STATS_ADD(sum0, ssq0, g0, g1)
            } else if (k == 1) {
                if (ty < 8) { STATS_ADD(sum0, ssq0, g0, g1) }
                else        { STATS_ADD(sum1, ssq1, g0, g1) }
            } else {
                if (ty < 8) STATS_ADD(sum1, ssq1, g0, g1)
            }
        }
        __syncthreads();
    }

    // ---- final step t=14: interior pairs only, write all 5 outputs ----
    {
        const float* Min = MB0;                 // t=14 even -> read MB0
        const float inv = 1.0f / (float)NSTEPS;

        #pragma unroll
        for (int k = 0; k < 3; ++k) {
            bool inter0 = (k == 0 && ty >= 8) || (k == 1 && ty < 8);
            bool inter1 = (k == 1 && ty >= 8) || (k == 2 && ty < 8);
            if (!inter0 && !inter1) continue;
            float* sumA = inter0 ? sum0 : sum1;
            float* ssqA = inter0 ? ssq0 : ssq1;

            const int r0  = r0a[k];
            const int ir0 = ir0a[k];

            float dv0[8], dv1[8];
            LOAD_DRIVE_RAW(ir0, dv0)
            LOAD_DRIVE_RAW(ir0 + 1, dv1)

            float acc0[8] = {0.f, 0.f, 0.f, 0.f, 0.f, 0.f, 0.f, 0.f};
            float acc1[8] = {0.f, 0.f, 0.f, 0.f, 0.f, 0.f, 0.f, 0.f};
            PAIR_CONV(Min, r0, acc0, acc1)

            #pragma unroll
            for (int half = 0; half < 2; ++half) {
                const float* acc = half ? acc1 : acc0;
                const float* dv  = half ? dv1  : dv0;
                const int off    = half * 8;
                long long idx = plane + (long long)(ir0 + half) * W + x0;

                float g[8], mean[8], var[8], del[8];
                #pragma unroll
                for (int i = 0; i < 8; ++i) {
                    g[i] = clampg(fmaf(BETA_P, dv[i], acc[i]));
                    float s  = sumA[off + i] + g[i];
                    float sq = fmaf(g[i], g[i], ssqA[off + i]);
                    mean[i] = s * inv;
                    var[i]  = fmaf(-mean[i], mean[i], sq * inv);
                    del[i]  = g[i] - dv[i];
                }
                *reinterpret_cast<float4*>(out + idx)                = make_float4(g[0], g[1], g[2], g[3]);
                *reinterpret_cast<float4*>(out + idx + 4)            = make_float4(g[4], g[5], g[6], g[7]);
                *reinterpret_cast<float4*>(out + NTOT + idx)         = make_float4(mean[0], mean[1], mean[2], mean[3]);
                *reinterpret_cast<float4*>(out + NTOT + idx + 4)     = make_float4(mean[4], mean[5], mean[6], mean[7]);
                *reinterpret_cast<float4*>(out + 2 * NTOT + idx)     = make_float4(var[0], var[1], var[2], var[3]);
                *reinterpret_cast<float4*>(out + 2 * NTOT + idx + 4) = make_float4(var[4], var[5], var[6], var[7]);
                *reinterpret_cast<float4*>(out + 3 * NTOT + idx)     = make_float4(del[0], del[1], del[2], del[3]);
                *reinterpret_cast<float4*>(out + 3 * NTOT + idx + 4) = make_float4(del[4], del[5], del[6], del[7]);
                *reinterpret_cast<float4*>(out + 4 * NTOT + idx)     = make_float4(del[0], del[1], del[2], del[3]);
                *reinterpret_cast<float4*>(out + 4 * NTOT + idx + 4) = make_float4(del[4], del[5], del[6], del[7]);
            }
        }
    }
}

extern "C" void kernel_launch(void* const* d_in, const int* in_sizes, int n_in,
                              void* d_out, int out_size)
{
    const float* drive  = (const float*)d_in[0];   // [16,8,256,256] f32
    const float* Klocal = (const float*)d_in[1];   // [8,1,3,3] f32
    float* out = (float*)d_out;                    // 5 x [16,8,256,256] f32

    const int smem_bytes = 2 * BROWS * W * (int)sizeof(float);   // 196608
    cudaFuncSetAttribute(cml_fused_kernel,
                         cudaFuncAttributeMaxDynamicSharedMemorySize, smem_bytes);

    dim3 grid(HIMG / STRIP, 8, 16);    // 4 strips x 8 ch x 16 batch = 512 CTAs
    dim3 block(TXN, TYN);              // 512 threads
    cml_fused_kernel<<<grid, block, smem_bytes>>>(drive, Klocal, out);
}